// round 2
// baseline (speedup 1.0000x reference)
#include <cuda_runtime.h>
#include <cuda_bf16.h>
#include <cstdint>

#define BB 8
#define LL 1024
#define NV 4096
#define DD 1024

// ---------------- scratch (device globals; no allocations) ----------------
__device__ __nv_bfloat16 g_tn[BB * LL * DD];   // normalized text, bf16 (16 MiB)
__device__ __nv_bfloat16 g_vn[BB * NV * DD];   // normalized visual, bf16 (64 MiB)
__device__ float g_rowsum[BB * LL];            // sum of exp(logit) per (b,l)
__device__ float g_bnorm[BB * LL];             // normalized beta weights

// ---------------- PTX helpers ----------------
__device__ __forceinline__ void cp_async16(void* s, const void* g) {
    uint32_t sa = (uint32_t)__cvta_generic_to_shared(s);
    asm volatile("cp.async.cg.shared.global [%0], [%1], 16;\n" :: "r"(sa), "l"(g));
}
__device__ __forceinline__ void cp_commit() { asm volatile("cp.async.commit_group;\n"); }
template <int N> __device__ __forceinline__ void cp_wait() {
    asm volatile("cp.async.wait_group %0;\n" :: "n"(N));
}
__device__ __forceinline__ void ldm4(uint32_t* r, const void* s) {
    uint32_t sa = (uint32_t)__cvta_generic_to_shared(s);
    asm volatile("ldmatrix.sync.aligned.m8n8.x4.shared.b16 {%0,%1,%2,%3}, [%4];\n"
                 : "=r"(r[0]), "=r"(r[1]), "=r"(r[2]), "=r"(r[3]) : "r"(sa));
}
__device__ __forceinline__ void mma_bf16(float* c, const uint32_t* a, const uint32_t* b) {
    asm volatile(
        "mma.sync.aligned.m16n8k16.row.col.f32.bf16.bf16.f32 "
        "{%0,%1,%2,%3}, {%4,%5,%6,%7}, {%8,%9}, {%0,%1,%2,%3};\n"
        : "+f"(c[0]), "+f"(c[1]), "+f"(c[2]), "+f"(c[3])
        : "r"(a[0]), "r"(a[1]), "r"(a[2]), "r"(a[3]), "r"(b[0]), "r"(b[1]));
}

// ---------------- K0: zero rowsum + s_ia ----------------
__global__ void k_zero(float* __restrict__ s_ia) {
    int i = blockIdx.x * blockDim.x + threadIdx.x;
    if (i < BB * NV) s_ia[i] = 0.0f;
    if (i < BB * LL) g_rowsum[i] = 0.0f;
}

// ---------------- K1: L2 normalize rows + convert fp32 -> bf16 ----------------
// one CTA (128 threads) per row of D=1024
__global__ void k_norm(const float* __restrict__ src, int which) {
    __nv_bfloat16* dst = which ? g_vn : g_tn;
    int row = blockIdx.x;
    const float4* p = (const float4*)(src + (size_t)row * DD);
    int t = threadIdx.x;

    float4 v0 = p[t];
    float4 v1 = p[t + 128];
    float ss = v0.x * v0.x + v0.y * v0.y + v0.z * v0.z + v0.w * v0.w +
               v1.x * v1.x + v1.y * v1.y + v1.z * v1.z + v1.w * v1.w;
    #pragma unroll
    for (int o = 16; o > 0; o >>= 1) ss += __shfl_xor_sync(0xffffffffu, ss, o);
    __shared__ float sred[4];
    if ((t & 31) == 0) sred[t >> 5] = ss;
    __syncthreads();
    float tot = sred[0] + sred[1] + sred[2] + sred[3];
    float rn = 1.0f / fmaxf(sqrtf(tot), 1e-12f);

    __nv_bfloat162* q = (__nv_bfloat162*)(dst + (size_t)row * DD);
    q[2 * t + 0]       = __floats2bfloat162_rn(v0.x * rn, v0.y * rn);
    q[2 * t + 1]       = __floats2bfloat162_rn(v0.z * rn, v0.w * rn);
    q[2 * t + 256]     = __floats2bfloat162_rn(v1.x * rn, v1.y * rn);
    q[2 * t + 257]     = __floats2bfloat162_rn(v1.z * rn, v1.w * rn);
}

// ---------------- K1b: beta normalization ----------------
__global__ void k_bnorm(const float* __restrict__ beta, const int* __restrict__ mask) {
    int b = blockIdx.x;
    int t = threadIdx.x;  // 256
    float vals[4];
    float local = 0.0f;
    #pragma unroll
    for (int j = 0; j < 4; j++) {
        int l = t + j * 256;
        float mf = (mask[b * LL + l] != 0) ? 1.0f : 0.0f;
        float v = beta[b * LL + l] * mf;
        vals[j] = v;
        local += v;
    }
    #pragma unroll
    for (int o = 16; o > 0; o >>= 1) local += __shfl_xor_sync(0xffffffffu, local, o);
    __shared__ float sr[8];
    if ((t & 31) == 0) sr[t >> 5] = local;
    __syncthreads();
    float tot = 0.0f;
    #pragma unroll
    for (int i = 0; i < 8; i++) tot += sr[i];
    float denom = tot + 1e-8f;
    #pragma unroll
    for (int j = 0; j < 4; j++) g_bnorm[b * LL + t + j * 256] = vals[j] / denom;
}

// ---------------- K2: bf16 GEMM + exp + atomic row sums ----------------
// C tile 128x128, BK=64, 256 threads = 8 warps (2 x 4), warp tile 64x32.
// Writes E = exp(logit) into the A region of d_out; atomicAdds row sums.
__global__ void __launch_bounds__(256, 1) k_gemm(float* __restrict__ Aout) {
    extern __shared__ __align__(16) char smem_raw[];
    uint4* sA = (uint4*)smem_raw;            // 2 x 1024 uint4 (32 KB)
    uint4* sB = (uint4*)(smem_raw + 32768);  // 2 x 1024 uint4 (32 KB)

    const int b = blockIdx.z, bm = blockIdx.y, bn = blockIdx.x;
    const int tid = threadIdx.x;
    const int lane = tid & 31, warp = tid >> 5;
    const int wm = warp >> 2, wn = warp & 3;

    const __nv_bfloat16* Ag = g_tn + (size_t)b * LL * DD + (size_t)bm * 128 * DD;
    const __nv_bfloat16* Bg = g_vn + (size_t)b * NV * DD + (size_t)bn * 128 * DD;

    const int lrow = tid >> 1;      // 0..127
    const int lhalf = tid & 1;      // 0..1 : which 32-elem half of the 64-wide k slab

    float acc[4][4][4];
    #pragma unroll
    for (int mi = 0; mi < 4; mi++)
        #pragma unroll
        for (int ni = 0; ni < 4; ni++)
            #pragma unroll
            for (int k = 0; k < 4; k++) acc[mi][ni][k] = 0.0f;

    auto prefetch = [&](int kt, int buf) {
        const uint4* gA = (const uint4*)(Ag + (size_t)lrow * DD + kt * 64 + lhalf * 32);
        const uint4* gB = (const uint4*)(Bg + (size_t)lrow * DD + kt * 64 + lhalf * 32);
        uint4* dA = sA + buf * 1024;
        uint4* dB = sB + buf * 1024;
        #pragma unroll
        for (int j = 0; j < 4; j++) {
            int c = lhalf * 4 + j;
            int phys = lrow * 8 + (c ^ (lrow & 7));
            cp_async16(&dA[phys], &gA[j]);
            cp_async16(&dB[phys], &gB[j]);
        }
    };

    prefetch(0, 0);
    cp_commit();

    const int NKT = DD / 64;  // 16
    for (int kt = 0; kt < NKT; kt++) {
        const int cur = kt & 1;
        if (kt + 1 < NKT) {
            prefetch(kt + 1, cur ^ 1);
            cp_commit();
            cp_wait<1>();
        } else {
            cp_wait<0>();
        }
        __syncthreads();

        const uint4* Ab = sA + cur * 1024;
        const uint4* Bb = sB + cur * 1024;
        #pragma unroll
        for (int ks = 0; ks < 4; ks++) {
            uint32_t af[4][4];
            uint32_t bf[4][2];
            #pragma unroll
            for (int mi = 0; mi < 4; mi++) {
                int row = wm * 64 + mi * 16 + (lane & 15);
                int c = ks * 2 + (lane >> 4);
                ldm4(af[mi], Ab + row * 8 + (c ^ (row & 7)));
            }
            #pragma unroll
            for (int pr = 0; pr < 2; pr++) {
                int g = lane >> 3;
                int row = wn * 32 + pr * 16 + (lane & 7) + (g >> 1) * 8;
                int c = ks * 2 + (g & 1);
                uint32_t r[4];
                ldm4(r, Bb + row * 8 + (c ^ (row & 7)));
                bf[pr * 2][0] = r[0];
                bf[pr * 2][1] = r[1];
                bf[pr * 2 + 1][0] = r[2];
                bf[pr * 2 + 1][1] = r[3];
            }
            #pragma unroll
            for (int mi = 0; mi < 4; mi++)
                #pragma unroll
                for (int ni = 0; ni < 4; ni++) mma_bf16(acc[mi][ni], af[mi], bf[ni]);
        }
        __syncthreads();
    }

    // epilogue: logit = dot/32, E = exp(logit); write E; accumulate row sums
    const float scale = 1.0f / 32.0f;
    float rsum[8];
    #pragma unroll
    for (int k = 0; k < 8; k++) rsum[k] = 0.0f;

    #pragma unroll
    for (int mi = 0; mi < 4; mi++) {
        #pragma unroll
        for (int half = 0; half < 2; half++) {
            int r = wm * 64 + mi * 16 + (lane >> 2) + half * 8;
            int gl = bm * 128 + r;
            size_t rowoff = ((size_t)b * LL + gl) * NV + bn * 128 + wn * 32 + (lane & 3) * 2;
            #pragma unroll
            for (int ni = 0; ni < 4; ni++) {
                float v0 = acc[mi][ni][half * 2 + 0];
                float v1 = acc[mi][ni][half * 2 + 1];
                float e0 = __expf(v0 * scale);
                float e1 = __expf(v1 * scale);
                rsum[mi * 2 + half] += e0 + e1;
                *(float2*)(Aout + rowoff + ni * 8) = make_float2(e0, e1);
            }
        }
    }
    #pragma unroll
    for (int k = 0; k < 8; k++) {
        float v = rsum[k];
        v += __shfl_xor_sync(0xffffffffu, v, 1);
        v += __shfl_xor_sync(0xffffffffu, v, 2);
        if ((lane & 3) == 0) {
            int mi = k >> 1, half = k & 1;
            int gl = bm * 128 + wm * 64 + mi * 16 + (lane >> 2) + half * 8;
            atomicAdd(&g_rowsum[b * LL + gl], v);
        }
    }
}

// ---------------- K3: A = E / rowsum (in place) + s_ia reduction ----------------
// grid (NV/1024, LL/64, BB), 256 threads; each thread owns 4 columns (float4)
__global__ void k_final(float* __restrict__ dout, const int* __restrict__ mask) {
    __shared__ float s_inv[64], s_w[64];
    const int b = blockIdx.z, ls = blockIdx.y, nt = blockIdx.x;
    const int t = threadIdx.x;

    if (t < 64) {
        int l = ls * 64 + t;
        float rs = g_rowsum[b * LL + l];
        float mf = (mask[b * LL + l] != 0) ? 1.0f : 0.0f;
        float inv = mf / rs;
        s_inv[t] = inv;
        s_w[t] = g_bnorm[b * LL + l] * inv;
    }
    __syncthreads();

    const int col = nt * 1024 + t * 4;
    float* Abase = dout + (size_t)BB * NV + ((size_t)b * LL + ls * 64) * NV + col;

    float4 acc = make_float4(0.0f, 0.0f, 0.0f, 0.0f);
    #pragma unroll 4
    for (int l = 0; l < 64; l++) {
        float4* p = (float4*)(Abase + (size_t)l * NV);
        float4 e = *p;
        float inv = s_inv[l], w = s_w[l];
        float4 a = make_float4(e.x * inv, e.y * inv, e.z * inv, e.w * inv);
        *p = a;
        acc.x += e.x * w;
        acc.y += e.y * w;
        acc.z += e.z * w;
        acc.w += e.w * w;
    }
    float* s = dout + (size_t)b * NV + col;
    atomicAdd(s + 0, acc.x);
    atomicAdd(s + 1, acc.y);
    atomicAdd(s + 2, acc.z);
    atomicAdd(s + 3, acc.w);
}

// ---------------- launch ----------------
extern "C" void kernel_launch(void* const* d_in, const int* in_sizes, int n_in,
                              void* d_out, int out_size) {
    const float* text = (const float*)d_in[0];
    const float* vis = (const float*)d_in[1];
    const float* beta = (const float*)d_in[2];
    const int* mask = (const int*)d_in[3];
    float* out = (float*)d_out;

    cudaFuncSetAttribute(k_gemm, cudaFuncAttributeMaxDynamicSharedMemorySize, 65536);

    k_zero<<<(BB * NV + 255) / 256, 256>>>(out);
    k_norm<<<BB * LL, 128>>>(text, 0);
    k_norm<<<BB * NV, 128>>>(vis, 1);
    k_bnorm<<<BB, 256>>>(beta, mask);
    k_gemm<<<dim3(NV / 128, LL / 128, BB), 256, 65536>>>(out + (size_t)BB * NV);
    k_final<<<dim3(NV / 1024, LL / 64, BB), 256>>>(out, mask);
}

// round 4
// speedup vs baseline: 1.2655x; 1.2655x over previous
#include <cuda_runtime.h>
#include <cuda_bf16.h>
#include <cuda_fp8.h>
#include <cstdint>

#define BB 8
#define LL 1024
#define NV 4096
#define DD 1024

// ---------------- scratch (device globals; no allocations) ----------------
__device__ uint8_t g_t8[BB * LL * DD];          // normalized text, e4m3 (8 MiB)
__device__ uint8_t g_v8[BB * NV * DD];          // normalized visual, e4m3 (32 MiB)
__device__ __nv_bfloat16 g_L[(size_t)BB * LL * NV];  // raw dot logits, bf16 (64 MiB)
__device__ float g_rowsum[BB * LL];             // sum of exp(logit) per (b,l)
__device__ float g_bnorm[BB * LL];              // normalized beta weights

// ---------------- PTX helpers ----------------
__device__ __forceinline__ void cp_async16(void* s, const void* g) {
    uint32_t sa = (uint32_t)__cvta_generic_to_shared(s);
    asm volatile("cp.async.cg.shared.global [%0], [%1], 16;\n" :: "r"(sa), "l"(g));
}
__device__ __forceinline__ void cp_commit() { asm volatile("cp.async.commit_group;\n"); }
template <int N> __device__ __forceinline__ void cp_wait() {
    asm volatile("cp.async.wait_group %0;\n" :: "n"(N));
}
__device__ __forceinline__ void ldm4(uint32_t* r, const void* s) {
    uint32_t sa = (uint32_t)__cvta_generic_to_shared(s);
    asm volatile("ldmatrix.sync.aligned.m8n8.x4.shared.b16 {%0,%1,%2,%3}, [%4];\n"
                 : "=r"(r[0]), "=r"(r[1]), "=r"(r[2]), "=r"(r[3]) : "r"(sa));
}
// fp8 e4m3 MMA: m16n8k32, f32 accum. Fragment layout over byte-pairs is identical
// to bf16 m16n8k16 over b16 elements -> reuse the same ldmatrix addressing.
__device__ __forceinline__ void mma_fp8(float* c, const uint32_t* a, const uint32_t* b) {
    asm volatile(
        "mma.sync.aligned.m16n8k32.row.col.f32.e4m3.e4m3.f32 "
        "{%0,%1,%2,%3}, {%4,%5,%6,%7}, {%8,%9}, {%0,%1,%2,%3};\n"
        : "+f"(c[0]), "+f"(c[1]), "+f"(c[2]), "+f"(c[3])
        : "r"(a[0]), "r"(a[1]), "r"(a[2]), "r"(a[3]), "r"(b[0]), "r"(b[1]));
}

// ---------------- K0: zero rowsum + s_ia ----------------
__global__ void k_zero(float* __restrict__ s_ia) {
    int i = blockIdx.x * blockDim.x + threadIdx.x;
    if (i < BB * NV) s_ia[i] = 0.0f;
    if (i < BB * LL) g_rowsum[i] = 0.0f;
}

// ---------------- K1: L2 normalize rows + convert fp32 -> e4m3 ----------------
// one CTA (128 threads) per row of D=1024
__global__ void k_norm(const float* __restrict__ src, int which) {
    uint8_t* dst = which ? g_v8 : g_t8;
    int row = blockIdx.x;
    const float4* p = (const float4*)(src + (size_t)row * DD);
    int t = threadIdx.x;

    float4 v0 = p[t];
    float4 v1 = p[t + 128];
    float ss = v0.x * v0.x + v0.y * v0.y + v0.z * v0.z + v0.w * v0.w +
               v1.x * v1.x + v1.y * v1.y + v1.z * v1.z + v1.w * v1.w;
    #pragma unroll
    for (int o = 16; o > 0; o >>= 1) ss += __shfl_xor_sync(0xffffffffu, ss, o);
    __shared__ float sred[4];
    if ((t & 31) == 0) sred[t >> 5] = ss;
    __syncthreads();
    float tot = sred[0] + sred[1] + sred[2] + sred[3];
    float rn = 1.0f / fmaxf(sqrtf(tot), 1e-12f);

    uint32_t* q = (uint32_t*)(dst + (size_t)row * DD);
    {
        __nv_fp8x2_storage_t lo = __nv_cvt_float2_to_fp8x2(
            make_float2(v0.x * rn, v0.y * rn), __NV_SATFINITE, __NV_E4M3);
        __nv_fp8x2_storage_t hi = __nv_cvt_float2_to_fp8x2(
            make_float2(v0.z * rn, v0.w * rn), __NV_SATFINITE, __NV_E4M3);
        q[t] = (uint32_t)lo | ((uint32_t)hi << 16);
    }
    {
        __nv_fp8x2_storage_t lo = __nv_cvt_float2_to_fp8x2(
            make_float2(v1.x * rn, v1.y * rn), __NV_SATFINITE, __NV_E4M3);
        __nv_fp8x2_storage_t hi = __nv_cvt_float2_to_fp8x2(
            make_float2(v1.z * rn, v1.w * rn), __NV_SATFINITE, __NV_E4M3);
        q[t + 128] = (uint32_t)lo | ((uint32_t)hi << 16);
    }
}

// ---------------- K1b: beta normalization ----------------
__global__ void k_bnorm(const float* __restrict__ beta, const int* __restrict__ mask) {
    int b = blockIdx.x;
    int t = threadIdx.x;  // 256
    float vals[4];
    float local = 0.0f;
    #pragma unroll
    for (int j = 0; j < 4; j++) {
        int l = t + j * 256;
        float mf = (mask[b * LL + l] != 0) ? 1.0f : 0.0f;
        float v = beta[b * LL + l] * mf;
        vals[j] = v;
        local += v;
    }
    #pragma unroll
    for (int o = 16; o > 0; o >>= 1) local += __shfl_xor_sync(0xffffffffu, local, o);
    __shared__ float sr[8];
    if ((t & 31) == 0) sr[t >> 5] = local;
    __syncthreads();
    float tot = 0.0f;
    #pragma unroll
    for (int i = 0; i < 8; i++) tot += sr[i];
    float denom = tot + 1e-8f;
    #pragma unroll
    for (int j = 0; j < 4; j++) g_bnorm[b * LL + t + j * 256] = vals[j] / denom;
}

// ---------------- K2: fp8 GEMM -> bf16 logits + exp row sums ----------------
// C tile 128x128, BK=128 fp8 (128B rows, same swizzle layout as before),
// 256 threads = 8 warps (2 x 4), warp tile 64x32. m16n8k32 fp8 MMA.
// Writes bf16 raw dot to g_L; atomicAdds exp row sums.
__global__ void __launch_bounds__(256, 2) k_gemm() {
    extern __shared__ __align__(16) char smem_raw[];
    uint4* sA = (uint4*)smem_raw;            // 2 x 1024 uint4 (32 KB)
    uint4* sB = (uint4*)(smem_raw + 32768);  // 2 x 1024 uint4 (32 KB)

    const int b = blockIdx.z, bm = blockIdx.y, bn = blockIdx.x;
    const int tid = threadIdx.x;
    const int lane = tid & 31, warp = tid >> 5;
    const int wm = warp >> 2, wn = warp & 3;

    const uint8_t* Ag = g_t8 + (size_t)b * LL * DD + (size_t)bm * 128 * DD;
    const uint8_t* Bg = g_v8 + (size_t)b * NV * DD + (size_t)bn * 128 * DD;

    const int lrow = tid >> 1;      // 0..127
    const int lhalf = tid & 1;      // which 64B half of the 128B k slab

    float acc[4][4][4];
    #pragma unroll
    for (int mi = 0; mi < 4; mi++)
        #pragma unroll
        for (int ni = 0; ni < 4; ni++)
            #pragma unroll
            for (int k = 0; k < 4; k++) acc[mi][ni][k] = 0.0f;

    auto prefetch = [&](int kt, int buf) {
        const uint4* gA = (const uint4*)(Ag + (size_t)lrow * DD + kt * 128 + lhalf * 64);
        const uint4* gB = (const uint4*)(Bg + (size_t)lrow * DD + kt * 128 + lhalf * 64);
        uint4* dA = sA + buf * 1024;
        uint4* dB = sB + buf * 1024;
        #pragma unroll
        for (int j = 0; j < 4; j++) {
            int c = lhalf * 4 + j;
            int phys = lrow * 8 + (c ^ (lrow & 7));
            cp_async16(&dA[phys], &gA[j]);
            cp_async16(&dB[phys], &gB[j]);
        }
    };

    prefetch(0, 0);
    cp_commit();

    const int NKT = DD / 128;  // 8
    for (int kt = 0; kt < NKT; kt++) {
        const int cur = kt & 1;
        if (kt + 1 < NKT) {
            prefetch(kt + 1, cur ^ 1);
            cp_commit();
            cp_wait<1>();
        } else {
            cp_wait<0>();
        }
        __syncthreads();

        const uint4* Ab = sA + cur * 1024;
        const uint4* Bb = sB + cur * 1024;
        #pragma unroll
        for (int ks = 0; ks < 4; ks++) {   // each ks = k32 fp8 = 16 b16 units = 2 chunks
            uint32_t af[4][4];
            uint32_t bf[4][2];
            #pragma unroll
            for (int mi = 0; mi < 4; mi++) {
                int row = wm * 64 + mi * 16 + (lane & 15);
                int c = ks * 2 + (lane >> 4);
                ldm4(af[mi], Ab + row * 8 + (c ^ (row & 7)));
            }
            #pragma unroll
            for (int pr = 0; pr < 2; pr++) {
                int g = lane >> 3;
                int row = wn * 32 + pr * 16 + (lane & 7) + (g >> 1) * 8;
                int c = ks * 2 + (g & 1);
                uint32_t r[4];
                ldm4(r, Bb + row * 8 + (c ^ (row & 7)));
                bf[pr * 2][0] = r[0];
                bf[pr * 2][1] = r[1];
                bf[pr * 2 + 1][0] = r[2];
                bf[pr * 2 + 1][1] = r[3];
            }
            #pragma unroll
            for (int mi = 0; mi < 4; mi++)
                #pragma unroll
                for (int ni = 0; ni < 4; ni++) mma_fp8(acc[mi][ni], af[mi], bf[ni]);
        }
        __syncthreads();
    }

    // epilogue: round dot to bf16 (stored), e = exp(bf16(dot)/32), accumulate rsum
    const float scale = 1.0f / 32.0f;
    float rsum[8];
    #pragma unroll
    for (int k = 0; k < 8; k++) rsum[k] = 0.0f;

    #pragma unroll
    for (int mi = 0; mi < 4; mi++) {
        #pragma unroll
        for (int half = 0; half < 2; half++) {
            int r = wm * 64 + mi * 16 + (lane >> 2) + half * 8;
            int gl = bm * 128 + r;
            size_t rowoff = ((size_t)b * LL + gl) * NV + bn * 128 + wn * 32 + (lane & 3) * 2;
            #pragma unroll
            for (int ni = 0; ni < 4; ni++) {
                __nv_bfloat162 v2 = __floats2bfloat162_rn(acc[mi][ni][half * 2 + 0],
                                                          acc[mi][ni][half * 2 + 1]);
                *(__nv_bfloat162*)(g_L + rowoff + ni * 8) = v2;
                float e0 = __expf(__bfloat162float(v2.x) * scale);
                float e1 = __expf(__bfloat162float(v2.y) * scale);
                rsum[mi * 2 + half] += e0 + e1;
            }
        }
    }
    #pragma unroll
    for (int k = 0; k < 8; k++) {
        float v = rsum[k];
        v += __shfl_xor_sync(0xffffffffu, v, 1);
        v += __shfl_xor_sync(0xffffffffu, v, 2);
        if ((lane & 3) == 0) {
            int mi = k >> 1, half = k & 1;
            int gl = bm * 128 + wm * 64 + mi * 16 + (lane >> 2) + half * 8;
            atomicAdd(&g_rowsum[b * LL + gl], v);
        }
    }
}

// ---------------- K3: A = exp(L/32)/rowsum + s_ia reduction ----------------
// grid (NV/1024, LL/64, BB), 256 threads; each thread owns 4 columns
__global__ void k_final(float* __restrict__ dout, const int* __restrict__ mask) {
    __shared__ float s_inv[64], s_w[64];
    const int b = blockIdx.z, ls = blockIdx.y, nt = blockIdx.x;
    const int t = threadIdx.x;

    if (t < 64) {
        int l = ls * 64 + t;
        float rs = g_rowsum[b * LL + l];
        float mf = (mask[b * LL + l] != 0) ? 1.0f : 0.0f;
        float inv = mf / rs;
        s_inv[t] = inv;
        s_w[t] = g_bnorm[b * LL + l] * inv;
    }
    __syncthreads();

    const float scale = 1.0f / 32.0f;
    const int col = nt * 1024 + t * 4;
    const __nv_bfloat16* Lbase = g_L + ((size_t)b * LL + ls * 64) * NV + col;
    float* Abase = dout + (size_t)BB * NV + ((size_t)b * LL + ls * 64) * NV + col;

    float4 acc = make_float4(0.0f, 0.0f, 0.0f, 0.0f);
    #pragma unroll 4
    for (int l = 0; l < 64; l++) {
        uint2 raw = *(const uint2*)(Lbase + (size_t)l * NV);
        __nv_bfloat162 p0 = *(__nv_bfloat162*)&raw.x;
        __nv_bfloat162 p1 = *(__nv_bfloat162*)&raw.y;
        float e0 = __expf(__bfloat162float(p0.x) * scale);
        float e1 = __expf(__bfloat162float(p0.y) * scale);
        float e2 = __expf(__bfloat162float(p1.x) * scale);
        float e3 = __expf(__bfloat162float(p1.y) * scale);
        float inv = s_inv[l], w = s_w[l];
        *(float4*)(Abase + (size_t)l * NV) =
            make_float4(e0 * inv, e1 * inv, e2 * inv, e3 * inv);
        acc.x += e0 * w;
        acc.y += e1 * w;
        acc.z += e2 * w;
        acc.w += e3 * w;
    }
    float* s = dout + (size_t)b * NV + col;
    atomicAdd(s + 0, acc.x);
    atomicAdd(s + 1, acc.y);
    atomicAdd(s + 2, acc.z);
    atomicAdd(s + 3, acc.w);
}

// ---------------- launch ----------------
extern "C" void kernel_launch(void* const* d_in, const int* in_sizes, int n_in,
                              void* d_out, int out_size) {
    const float* text = (const float*)d_in[0];
    const float* vis = (const float*)d_in[1];
    const float* beta = (const float*)d_in[2];
    const int* mask = (const int*)d_in[3];
    float* out = (float*)d_out;

    cudaFuncSetAttribute(k_gemm, cudaFuncAttributeMaxDynamicSharedMemorySize, 65536);

    k_zero<<<(BB * NV + 255) / 256, 256>>>(out);
    k_norm<<<BB * LL, 128>>>(text, 0);
    k_norm<<<BB * NV, 128>>>(vis, 1);
    k_bnorm<<<BB, 256>>>(beta, mask);
    k_gemm<<<dim3(NV / 128, LL / 128, BB), 256, 65536>>>();
    k_final<<<dim3(NV / 1024, LL / 64, BB), 256>>>(out, mask);
}